// round 1
// baseline (speedup 1.0000x reference)
#include <cuda_runtime.h>
#include <cuda_bf16.h>
#include <math_constants.h>
#include <limits.h>

// Segment-max pooling with sorted segment ids.
// One warp owns CHUNK consecutive rows; lane = channel (C == 32).
// A warp is "responsible" for a segment iff the segment's FIRST row lies in
// its chunk; it scans forward past the chunk end to finish the segment, then
// does a single plain store (no atomics, no init pass). Empty segments are
// the gaps between consecutive ids and are zeroed by the writer of the
// preceding segment (leading gap by the r0==0 warp).

#define CHUNK 64

__global__ __launch_bounds__(256) void seg_max_kernel(
    const float* __restrict__ feat,
    const int*   __restrict__ ids,
    float*       __restrict__ out,
    int N, int M)
{
    const unsigned FULL = 0xFFFFFFFFu;
    const int lane = threadIdx.x & 31;
    const int warp = blockIdx.x * (blockDim.x >> 5) + (threadIdx.x >> 5);

    const long long r0 = (long long)warp * CHUNK;
    if (r0 >= N) return;
    const int nrows = (int)(((long long)N - r0 < CHUNK) ? (N - r0) : CHUNK);

    // Coalesced load of this chunk's segment ids (2 x 32 lanes).
    int id_lo = (lane < nrows)      ? ids[r0 + lane]      : 0;
    int id_hi = (32 + lane < nrows) ? ids[r0 + 32 + lane] : 0;

    // id of the row just before our chunk (uniform broadcast load).
    const int prev_id = (r0 > 0) ? ids[r0 - 1] : -1;

    int   cur         = __shfl_sync(FULL, id_lo, 0);
    bool  responsible = (cur != prev_id);
    float m           = -CUDART_INF_F;

    const float* fptr = feat + r0 * 32 + lane;

    #pragma unroll
    for (int i = 0; i < CHUNK; ++i) {
        if (i >= nrows) break;  // uniform across warp
        int id = __shfl_sync(FULL, (i < 32) ? id_lo : id_hi, i & 31);
        if (id != cur) {
            if (responsible) {
                out[(long long)cur * 32 + lane] = m;
                // zero empty segments in the gap (cur, id)
                for (int g = cur + 1; g < id; ++g)
                    out[(long long)g * 32 + lane] = 0.0f;
            }
            cur = id;
            m = -CUDART_INF_F;
            responsible = true;
        }
        m = fmaxf(m, fptr[(long long)i * 32]);
    }

    // Finish the last segment we're responsible for: it may continue past r1.
    long long r = r0 + nrows;
    if (responsible) {
        while (r < N) {
            int id = ids[r];            // uniform broadcast load
            if (id != cur) break;
            m = fmaxf(m, feat[r * 32 + lane]);
            ++r;
        }
        out[(long long)cur * 32 + lane] = m;
        int next_id = (r < N) ? ids[r] : M;
        for (int g = cur + 1; g < next_id; ++g)
            out[(long long)g * 32 + lane] = 0.0f;
    }

    // Leading gap: segments before ids[0] are empty.
    if (r0 == 0) {
        int first = ids[0];
        for (int g = 0; g < first; ++g)
            out[(long long)g * 32 + lane] = 0.0f;
    }
}

extern "C" void kernel_launch(void* const* d_in, const int* in_sizes, int n_in,
                              void* d_out, int out_size) {
    const float* feat = (const float*)d_in[0];
    const int*   ids  = (const int*)d_in[1];
    float*       out  = (float*)d_out;

    const int N = in_sizes[1];        // number of rows (= len(segment_ids))
    const int M = out_size / 32;      // number of segments (C == 32)

    const int warps   = (N + CHUNK - 1) / CHUNK;
    const int threads = 256;
    const int blocks  = (warps * 32 + threads - 1) / threads;

    seg_max_kernel<<<blocks, threads>>>(feat, ids, out, N, M);
}

// round 2
// speedup vs baseline: 2.2809x; 2.2809x over previous
#include <cuda_runtime.h>
#include <cuda_bf16.h>
#include <math_constants.h>
#include <limits.h>

// Segment-max pooling with sorted segment ids (N rows x 32 ch -> M segments).
// One warp owns CHUNK consecutive rows; lane = channel.
// Feature loads are batched (BATCH independent LDGs) ahead of the
// boundary-handling loop so the memory pipe sees MLP=BATCH per warp.
// A warp is responsible for a segment iff the segment's first row lies in its
// chunk; it extends past the chunk end via ballot-scanned id blocks, then does
// one plain store. Gaps between consecutive ids are empty segments -> 0.

#define CHUNK 64
#define BATCH 8

__global__ __launch_bounds__(256) void seg_max_kernel(
    const float* __restrict__ feat,
    const int*   __restrict__ ids,
    float*       __restrict__ out,
    int N, int M)
{
    const unsigned FULL = 0xFFFFFFFFu;
    const int lane = threadIdx.x & 31;
    const int warp = blockIdx.x * (blockDim.x >> 5) + (threadIdx.x >> 5);

    const long long r0 = (long long)warp * CHUNK;
    if (r0 >= N) return;
    const int nrows = (int)(((long long)N - r0 < CHUNK) ? (N - r0) : CHUNK);

    // Coalesced load of this chunk's segment ids (2 x 32 lanes).
    int id_lo = (lane < nrows)      ? ids[r0 + lane]      : 0;
    int id_hi = (32 + lane < nrows) ? ids[r0 + 32 + lane] : 0;

    // id of the row just before our chunk.
    const int prev_id = (r0 > 0) ? ids[r0 - 1] : -1;

    int   cur         = __shfl_sync(FULL, id_lo, 0);
    bool  responsible = (cur != prev_id);
    float m           = -CUDART_INF_F;

    const float* fptr = feat + r0 * 32 + lane;

    if (nrows == CHUNK) {
        // Fast path: full chunk. Batch loads, then apply boundary logic.
        #pragma unroll
        for (int base = 0; base < CHUNK; base += BATCH) {
            float v[BATCH];
            #pragma unroll
            for (int j = 0; j < BATCH; ++j)
                v[j] = fptr[(long long)(base + j) * 32];

            #pragma unroll
            for (int j = 0; j < BATCH; ++j) {
                const int i = base + j;
                int id = __shfl_sync(FULL, (i < 32) ? id_lo : id_hi, i & 31);
                if (id != cur) {              // warp-uniform branch
                    if (responsible) {
                        out[(long long)cur * 32 + lane] = m;
                        for (int g = cur + 1; g < id; ++g)
                            out[(long long)g * 32 + lane] = 0.0f;
                    }
                    cur = id;
                    m = -CUDART_INF_F;
                    responsible = true;
                }
                m = fmaxf(m, v[j]);
            }
        }
    } else {
        // Ragged last chunk: simple scalar path (one warp in the grid).
        for (int i = 0; i < nrows; ++i) {
            int id = __shfl_sync(FULL, (i < 32) ? id_lo : id_hi, i & 31);
            if (id != cur) {
                if (responsible) {
                    out[(long long)cur * 32 + lane] = m;
                    for (int g = cur + 1; g < id; ++g)
                        out[(long long)g * 32 + lane] = 0.0f;
                }
                cur = id;
                m = -CUDART_INF_F;
                responsible = true;
            }
            m = fmaxf(m, fptr[(long long)i * 32]);
        }
    }

    // Finish the last segment we own: it may continue past the chunk end.
    long long r = r0 + nrows;
    if (responsible) {
        while (r < N) {                       // uniform condition
            long long rl = r + lane;
            int idn = (rl < N) ? ids[rl] : (cur + 1);   // sentinel != cur
            unsigned diff = __ballot_sync(FULL, idn != cur);
            int k = diff ? (__ffs(diff) - 1) : 32;      // continuation rows
            for (int j = 0; j < k; ++j)                 // independent loads
                m = fmaxf(m, feat[(r + j) * 32 + lane]);
            r += k;
            if (k < 32) break;
        }
        out[(long long)cur * 32 + lane] = m;
        int next_id = (r < N) ? ids[r] : M;
        for (int g = cur + 1; g < next_id; ++g)
            out[(long long)g * 32 + lane] = 0.0f;
    }

    // Leading gap: segments before ids[0] are empty.
    if (r0 == 0) {
        int first = ids[0];
        for (int g = 0; g < first; ++g)
            out[(long long)g * 32 + lane] = 0.0f;
    }
}

extern "C" void kernel_launch(void* const* d_in, const int* in_sizes, int n_in,
                              void* d_out, int out_size) {
    const float* feat = (const float*)d_in[0];
    const int*   ids  = (const int*)d_in[1];
    float*       out  = (float*)d_out;

    const int N = in_sizes[1];
    const int M = out_size / 32;

    const int warps   = (N + CHUNK - 1) / CHUNK;
    const int threads = 256;
    const int blocks  = (warps * 32 + threads - 1) / threads;

    seg_max_kernel<<<blocks, threads>>>(feat, ids, out, N, M);
}